// round 3
// baseline (speedup 1.0000x reference)
#include <cuda_runtime.h>

#define C_DIM 64
#define ROWS_PER_BLOCK 256
#define MARGIN_F 0.01f
#define MAX_PARTIALS 4096

// 1/(C - i) table; overall 1/B factor applied once in the reduce kernel.
#define T1(i) (1.0f / (64.0f - (float)(i)))
#define T4(i) T1(i), T1((i)+1), T1((i)+2), T1((i)+3)
#define T16(i) T4(i), T4((i)+4), T4((i)+8), T4((i)+12)
__constant__ float c_invgap[C_DIM] = { T16(0), T16(16), T16(32), T16(48) };

__device__ float g_partials[MAX_PARTIALS];

__global__ void __launch_bounds__(ROWS_PER_BLOCK)
margin_loss_kernel(const float* __restrict__ cand,
                   const float* __restrict__ summ,
                   int B)
{
    const int row = blockIdx.x * ROWS_PER_BLOCK + threadIdx.x;

    float a[C_DIM];
    float total = 0.0f;

    if (row < B) {
        // Coalesced-enough vector loads: 16x LDG.128, front-batched by ptxas.
        const float4* rp = reinterpret_cast<const float4*>(cand + (size_t)row * C_DIM);
        #pragma unroll
        for (int i = 0; i < C_DIM / 4; i++) {
            float4 v = rp[i];
            a[4 * i + 0] = v.x;
            a[4 * i + 1] = v.y;
            a[4 * i + 2] = v.z;
            a[4 * i + 3] = v.w;
        }

        // Summary term: mean(relu(cand - summary)) -> weight 1/C here, 1/B later.
        const float s = summ[row];
        float s0 = 0.0f, s1 = 0.0f;
        #pragma unroll
        for (int x = 0; x < C_DIM; x += 2) {
            s0 += fmaxf(a[x]     - s, 0.0f);
            s1 += fmaxf(a[x + 1] - s, 0.0f);
        }
        total = (s0 + s1) * (1.0f / (float)C_DIM);

        // Fold margin into operands: a[x] += MARGIN * x, so every pair term is
        // relu(a[j+i] - a[j]).
        #pragma unroll
        for (int x = 0; x < C_DIM; x++)
            a[x] = __fmaf_rn(MARGIN_F, (float)x, a[x]);

        // All gaps i = 1..C-1. Two accumulators break the FADD chain.
        #pragma unroll
        for (int i = 1; i < C_DIM; i++) {
            float b0 = 0.0f, b1 = 0.0f;
            #pragma unroll
            for (int j = 0; j + i < C_DIM; j += 2) {
                // d = a[j+i] - a[j] coaxed to FFMA-imm (rt_SMSP=1)
                float d0 = __fmaf_rn(a[j], -1.0f, a[j + i]);
                float r0 = fmaxf(d0, 0.0f);
                b0 = __fmaf_rn(r0, 1.0f, b0);
                if (j + 1 + i < C_DIM) {
                    float d1 = __fmaf_rn(a[j + 1], -1.0f, a[j + 1 + i]);
                    float r1 = fmaxf(d1, 0.0f);
                    b1 = __fmaf_rn(r1, 1.0f, b1);
                }
            }
            total = __fmaf_rn(b0 + b1, c_invgap[i], total);
        }
    }

    // Deterministic block reduction.
    __shared__ float sred[ROWS_PER_BLOCK];
    sred[threadIdx.x] = total;
    __syncthreads();
    #pragma unroll
    for (int off = ROWS_PER_BLOCK / 2; off > 0; off >>= 1) {
        if (threadIdx.x < off)
            sred[threadIdx.x] += sred[threadIdx.x + off];
        __syncthreads();
    }
    if (threadIdx.x == 0)
        g_partials[blockIdx.x] = sred[0];
}

__global__ void __launch_bounds__(512)
reduce_kernel(float* __restrict__ out, int nblocks, float invB)
{
    __shared__ float sred[512];
    float v = 0.0f;
    for (int i = threadIdx.x; i < nblocks; i += 512)
        v += g_partials[i];
    sred[threadIdx.x] = v;
    __syncthreads();
    #pragma unroll
    for (int off = 256; off > 0; off >>= 1) {
        if (threadIdx.x < off)
            sred[threadIdx.x] += sred[threadIdx.x + off];
        __syncthreads();
    }
    if (threadIdx.x == 0)
        out[0] = sred[0] * invB;
}

extern "C" void kernel_launch(void* const* d_in, const int* in_sizes, int n_in,
                              void* d_out, int out_size)
{
    const float* cand = (const float*)d_in[0];   // [B, 64] f32
    const float* summ = (const float*)d_in[1];   // [B]     f32
    float* out = (float*)d_out;

    const int B = in_sizes[1];
    const int nblocks = (B + ROWS_PER_BLOCK - 1) / ROWS_PER_BLOCK;
    const float invB = 1.0f / (float)B;

    margin_loss_kernel<<<nblocks, ROWS_PER_BLOCK>>>(cand, summ, B);
    reduce_kernel<<<1, 512>>>(out, nblocks, invB);
}

// round 5
// speedup vs baseline: 1.4237x; 1.4237x over previous
#include <cuda_runtime.h>

#define C_DIM   64
#define TPB     128
#define MARGIN_F 0.01f
#define MAX_BLOCKS 8192

// w2(i) = 0.5 / (C - i)  -- per-gap weight including the 0.5 from relu = (d+|d|)/2
#define W2(i) (0.5f / (64.0f - (float)(i)))
// Coefficient of prefix sum P[x] in the telescoped analytic part:
// sum_i w2(i)*T_i = S*w2sum - sum_{x=0}^{62} (w2(x+1)+w2(63-x)) * P[x]
#define CPX(x) (-(W2((x) + 1) + W2(63 - (x))))

__device__ float        g_partials[MAX_BLOCKS];
__device__ unsigned int g_sem = 0;

// ---- packed f32x2 helpers (Blackwell sm_100+) ----
__device__ __forceinline__ unsigned long long pk2(float lo, float hi) {
    unsigned long long r;
    asm("mov.b64 %0, {%1, %2};" : "=l"(r) : "f"(lo), "f"(hi));
    return r;
}
__device__ __forceinline__ void upk2(unsigned long long v, float& lo, float& hi) {
    asm("mov.b64 {%0, %1}, %2;" : "=f"(lo), "=f"(hi) : "l"(v));
}
__device__ __forceinline__ unsigned long long fma2(unsigned long long a,
                                                   unsigned long long b,
                                                   unsigned long long c) {
    unsigned long long r;
    asm("fma.rn.f32x2 %0, %1, %2, %3;" : "=l"(r) : "l"(a), "l"(b), "l"(c));
    return r;
}
__device__ __forceinline__ unsigned long long add2(unsigned long long a,
                                                   unsigned long long b) {
    unsigned long long r;
    asm("add.rn.f32x2 %0, %1, %2;" : "=l"(r) : "l"(a), "l"(b));
    return r;
}
__device__ __forceinline__ unsigned long long abs2(unsigned long long a) {
    return a & 0x7FFFFFFF7FFFFFFFULL;   // 2x LOP3, alu pipe
}

__global__ void __launch_bounds__(TPB)
margin_loss_kernel(const float* __restrict__ cand,
                   const float* __restrict__ summ,
                   float* __restrict__ out,
                   int B, float w2sum, float invB)
{
    const int row = blockIdx.x * TPB + threadIdx.x;

    float total = 0.0f;

    if (row < B) {
        float a[C_DIM];
        const float4* rp = reinterpret_cast<const float4*>(cand + (size_t)row * C_DIM);
        #pragma unroll
        for (int i = 0; i < C_DIM / 4; i++) {
            float4 v = rp[i];
            a[4 * i + 0] = v.x;
            a[4 * i + 1] = v.y;
            a[4 * i + 2] = v.z;
            a[4 * i + 3] = v.w;
        }

        // ---- summary term (uses UNfolded scores): mean relu(a - s), weight 1/C ----
        const float s = summ[row];
        float s0 = 0.0f, s1 = 0.0f;
        #pragma unroll
        for (int x = 0; x < C_DIM; x += 2) {
            s0 += fmaxf(a[x]     - s, 0.0f);
            s1 += fmaxf(a[x + 1] - s, 0.0f);
        }
        total = (s0 + s1) * (1.0f / (float)C_DIM);

        // ---- fold margin: a[x] += MARGIN * x  => pair term is relu(a[k]-a[j]) ----
        #pragma unroll
        for (int x = 0; x < C_DIM; x++)
            a[x] = __fmaf_rn(MARGIN_F, (float)x, a[x]);

        // ---- analytic telescoped part: sum_i w2(i) * sum_j (a[j+i]-a[j]) ----
        // via prefix sums with compile-time immediate coefficients.
        {
            float p = 0.0f, an = 0.0f;
            #pragma unroll
            for (int x = 0; x < 63; x++) {
                p = p + a[x];
                an = __fmaf_rn(CPX(x), p, an);
            }
            p = p + a[63];                       // p == S (full row sum)
            total = total + an;
            total = __fmaf_rn(p, w2sum, total);
        }

        // ---- pack: V[k] = {a[2k], a[2k+1]},  W[k] = {a[2k+1], a[2k+2]} ----
        unsigned long long V[32], W[31];
        #pragma unroll
        for (int k = 0; k < 32; k++) V[k] = pk2(a[2 * k], a[2 * k + 1]);
        #pragma unroll
        for (int k = 0; k < 31; k++) W[k] = pk2(a[2 * k + 1], a[2 * k + 2]);
        const float a63 = a[63];

        const unsigned long long NEG1 = pk2(-1.0f, -1.0f);

        // ---- even gaps i = 2m: |d| sums, d = V[g+m] - V[g] (packed, aligned) ----
        #pragma unroll
        for (int m = 1; m < 32; m++) {
            unsigned long long acc0 = 0ULL, acc1 = 0ULL;
            #pragma unroll
            for (int g = 0; g + m < 32; g += 2) {
                acc0 = add2(acc0, abs2(fma2(V[g], NEG1, V[g + m])));
                if (g + 1 + m < 32)
                    acc1 = add2(acc1, abs2(fma2(V[g + 1], NEG1, V[g + 1 + m])));
            }
            float x0, y0, x1, y1;
            upk2(acc0, x0, y0);
            upk2(acc1, x1, y1);
            total = __fmaf_rn((x0 + y0) + (x1 + y1), W2(2 * m), total);
        }

        // ---- odd gaps i = 2m+1: d = W[g+m] - V[g] (packed), + 1 scalar edge ----
        #pragma unroll
        for (int m = 0; m < 32; m++) {
            unsigned long long acc0 = 0ULL, acc1 = 0ULL;
            #pragma unroll
            for (int g = 0; g + m < 31; g += 2) {
                acc0 = add2(acc0, abs2(fma2(V[g], NEG1, W[g + m])));
                if (g + 1 + m < 31)
                    acc1 = add2(acc1, abs2(fma2(V[g + 1], NEG1, W[g + 1 + m])));
            }
            // edge pair: j = 63-i (even), k = 63:  d = a[63] - a[62-2m]
            float elo, ehi;
            upk2(V[31 - m], elo, ehi);
            float ds = fabsf(a63 - elo);
            float x0, y0, x1, y1;
            upk2(acc0, x0, y0);
            upk2(acc1, x1, y1);
            total = __fmaf_rn(((x0 + y0) + (x1 + y1)) + ds, W2(2 * m + 1), total);
        }
    }

    // ---- deterministic block reduction ----
    __shared__ float sred[TPB];
    __shared__ bool  amLast;
    sred[threadIdx.x] = total;
    __syncthreads();
    #pragma unroll
    for (int off = TPB / 2; off > 0; off >>= 1) {
        if (threadIdx.x < off)
            sred[threadIdx.x] += sred[threadIdx.x + off];
        __syncthreads();
    }
    if (threadIdx.x == 0) {
        g_partials[blockIdx.x] = sred[0];
        __threadfence();
        unsigned int t = atomicAdd(&g_sem, 1u);
        amLast = (t == gridDim.x - 1);
    }
    __syncthreads();

    // ---- last arriving block does the final (deterministic-order) reduce ----
    if (amLast) {
        float v = 0.0f;
        for (int i = threadIdx.x; i < (int)gridDim.x; i += TPB)
            v += g_partials[i];
        sred[threadIdx.x] = v;
        __syncthreads();
        #pragma unroll
        for (int off = TPB / 2; off > 0; off >>= 1) {
            if (threadIdx.x < off)
                sred[threadIdx.x] += sred[threadIdx.x + off];
            __syncthreads();
        }
        if (threadIdx.x == 0) {
            out[0] = sred[0] * invB;
            g_sem = 0;   // reset for next graph replay
        }
    }
}

extern "C" void kernel_launch(void* const* d_in, const int* in_sizes, int n_in,
                              void* d_out, int out_size)
{
    const float* cand = (const float*)d_in[0];   // [B, 64] f32
    const float* summ = (const float*)d_in[1];   // [B]     f32
    float* out = (float*)d_out;

    const int B = in_sizes[1];
    int nblocks = (B + TPB - 1) / TPB;
    if (nblocks > MAX_BLOCKS) nblocks = MAX_BLOCKS;  // shapes here: 1024

    // w2sum = sum_{i=1}^{63} 0.5/(64-i)
    double ws = 0.0;
    for (int i = 1; i < C_DIM; i++) ws += 0.5 / (double)(C_DIM - i);
    const float w2sum = (float)ws;
    const float invB  = 1.0f / (float)B;

    margin_loss_kernel<<<nblocks, TPB>>>(cand, summ, out, B, w2sum, invB);
}